// round 1
// baseline (speedup 1.0000x reference)
#include <cuda_runtime.h>
#include <math_constants.h>

#define HID   1024
#define BATCH 2
#define SKV   4096
#define SQ    512
#define NH    16
#define NHK   4
#define DH    64

// ---------------- scratch (no allocations allowed) ----------------
__device__ float g_Q [BATCH * SQ  * NH  * DH];  // [B*Sq , H*D ]
__device__ float g_K [BATCH * SKV * NHK * DH];  // [B*Skv, Hk*D]
__device__ float g_V [BATCH * SKV * NHK * DH];
__device__ float g_AO[BATCH * SQ  * NH  * DH];  // attention output

// ----------------------------------------------------------------------
// C[M,N] = A[M,K] @ W[N,K]^T, optionally fused per-64-col RMSNorm epilogue.
// BM=BN=64, BK=16, 256 threads, 4x4 microtile per thread.
// Requires M%64==0, N%64==0, K%16==0 (all true here).
// ----------------------------------------------------------------------
template <bool NORM>
__global__ void gemm_rt(const float* __restrict__ A,
                        const float* __restrict__ W,
                        const float* __restrict__ nw,
                        float* __restrict__ C,
                        int M, int N, int Kdim)
{
    __shared__ float As[16][64];
    __shared__ float Ws[16][64];
    __shared__ float scale_s[64];
    __shared__ float red[64 * 16];

    const int tid = threadIdx.x;
    const int tx  = tid & 15;
    const int ty  = tid >> 4;
    const int m0  = blockIdx.y * 64;
    const int n0  = blockIdx.x * 64;

    const int lr = tid >> 2;        // 0..63 (row within tile)
    const int lk = (tid & 3) * 4;   // 0,4,8,12 (k offset)

    const float* Ap = A + (size_t)(m0 + lr) * Kdim + lk;
    const float* Wp = W + (size_t)(n0 + lr) * Kdim + lk;

    float acc[4][4];
#pragma unroll
    for (int i = 0; i < 4; i++)
#pragma unroll
        for (int j = 0; j < 4; j++) acc[i][j] = 0.f;

    for (int kt = 0; kt < Kdim; kt += 16) {
        float4 a = *(const float4*)(Ap + kt);
        float4 w = *(const float4*)(Wp + kt);
        As[lk + 0][lr] = a.x; As[lk + 1][lr] = a.y;
        As[lk + 2][lr] = a.z; As[lk + 3][lr] = a.w;
        Ws[lk + 0][lr] = w.x; Ws[lk + 1][lr] = w.y;
        Ws[lk + 2][lr] = w.z; Ws[lk + 3][lr] = w.w;
        __syncthreads();
#pragma unroll
        for (int kk = 0; kk < 16; kk++) {
            float4 ra = *(const float4*)&As[kk][ty * 4];
            float4 rw = *(const float4*)&Ws[kk][tx * 4];
            float am[4] = {ra.x, ra.y, ra.z, ra.w};
            float wn[4] = {rw.x, rw.y, rw.z, rw.w};
#pragma unroll
            for (int i = 0; i < 4; i++)
#pragma unroll
                for (int j = 0; j < 4; j++) acc[i][j] += am[i] * wn[j];
        }
        __syncthreads();
    }

    if (NORM) {
        // per-row sum of squares over this 64-wide head block
#pragma unroll
        for (int i = 0; i < 4; i++) {
            float p = 0.f;
#pragma unroll
            for (int j = 0; j < 4; j++) p += acc[i][j] * acc[i][j];
            red[(ty * 4 + i) * 16 + tx] = p;
        }
        __syncthreads();
        if (tid < 64) {
            float s = 0.f;
#pragma unroll
            for (int t2 = 0; t2 < 16; t2++) s += red[tid * 16 + t2];
            scale_s[tid] = rsqrtf(s * (1.0f / 64.0f) + 1e-6f);
        }
        __syncthreads();
        float nwv[4];
#pragma unroll
        for (int j = 0; j < 4; j++) nwv[j] = nw[tx * 4 + j];
#pragma unroll
        for (int i = 0; i < 4; i++) {
            float sc = scale_s[ty * 4 + i];
#pragma unroll
            for (int j = 0; j < 4; j++) acc[i][j] *= sc * nwv[j];
        }
    }

#pragma unroll
    for (int i = 0; i < 4; i++) {
        int row = m0 + ty * 4 + i;
        float4 o = make_float4(acc[i][0], acc[i][1], acc[i][2], acc[i][3]);
        *(float4*)(C + (size_t)row * N + n0 + tx * 4) = o;
    }
}

// ----------------------------------------------------------------------
// Flash attention: block = 64 q rows of one (b, h). Streams 64-wide KV
// tiles, online softmax. 256 threads (16x16), thread owns rows
// {ty+16i} x cols {tx+16j} -> conflict-free scalar LDS with pitch 65.
// ----------------------------------------------------------------------
__global__ void attn_kernel(const float* __restrict__ Q,
                            const float* __restrict__ Kp,
                            const float* __restrict__ Vp,
                            float* __restrict__ Op)
{
    extern __shared__ float sm[];
    float* Qs   = sm;                 // 64*65
    float* Ks   = Qs + 64 * 65;
    float* Vs   = Ks + 64 * 65;
    float* Ps   = Vs + 64 * 65;
    float* m_s  = Ps + 64 * 65;       // 64
    float* l_s  = m_s + 64;           // 64
    float* al_s = l_s + 64;           // 64
    float* red  = al_s + 64;          // 64*16

    const int tid = threadIdx.x;
    const int tx  = tid & 15;
    const int ty  = tid >> 4;
    const int b   = blockIdx.z;
    const int h   = blockIdx.y;
    const int hk  = h >> 2;           // G = 4
    const int q0  = blockIdx.x * 64;

    // load Q tile [64 x 64]
    for (int idx = tid; idx < 64 * 16; idx += 256) {
        int r = idx >> 4, c = (idx & 15) * 4;
        float4 v = *(const float4*)(Q + (size_t)(b * SQ + q0 + r) * HID + h * DH + c);
        Qs[r * 65 + c + 0] = v.x; Qs[r * 65 + c + 1] = v.y;
        Qs[r * 65 + c + 2] = v.z; Qs[r * 65 + c + 3] = v.w;
    }
    if (tid < 64) { m_s[tid] = -CUDART_INF_F; l_s[tid] = 0.f; }

    float o[4][4];
#pragma unroll
    for (int i = 0; i < 4; i++)
#pragma unroll
        for (int j = 0; j < 4; j++) o[i][j] = 0.f;

    for (int t = 0; t < SKV / 64; t++) {
        // load K,V tiles [64 kv x 64 d]
        for (int idx = tid; idx < 64 * 16; idx += 256) {
            int r = idx >> 4, c = (idx & 15) * 4;
            size_t g = (size_t)(b * SKV + t * 64 + r) * (NHK * DH) + hk * DH + c;
            float4 kv4 = *(const float4*)(Kp + g);
            Ks[r * 65 + c + 0] = kv4.x; Ks[r * 65 + c + 1] = kv4.y;
            Ks[r * 65 + c + 2] = kv4.z; Ks[r * 65 + c + 3] = kv4.w;
            float4 vv4 = *(const float4*)(Vp + g);
            Vs[r * 65 + c + 0] = vv4.x; Vs[r * 65 + c + 1] = vv4.y;
            Vs[r * 65 + c + 2] = vv4.z; Vs[r * 65 + c + 3] = vv4.w;
        }
        __syncthreads();   // (1) tiles ready

        // S = Q @ K^T, thread tile [rows ty+16i][cols tx+16j]
        float s[4][4];
#pragma unroll
        for (int i = 0; i < 4; i++)
#pragma unroll
            for (int j = 0; j < 4; j++) s[i][j] = 0.f;
        for (int d = 0; d < DH; d++) {
            float qv[4], kv[4];
#pragma unroll
            for (int i = 0; i < 4; i++) qv[i] = Qs[(ty + 16 * i) * 65 + d];
#pragma unroll
            for (int j = 0; j < 4; j++) kv[j] = Ks[(tx + 16 * j) * 65 + d];
#pragma unroll
            for (int i = 0; i < 4; i++)
#pragma unroll
                for (int j = 0; j < 4; j++) s[i][j] += qv[i] * kv[j];
        }

        // per-thread row maxes -> smem reduce
#pragma unroll
        for (int i = 0; i < 4; i++) {
            float tm = s[i][0];
#pragma unroll
            for (int j = 1; j < 4; j++) tm = fmaxf(tm, s[i][j]);
            red[(ty + 16 * i) * 16 + tx] = tm;
        }
        __syncthreads();   // (2)
        if (tid < 64) {
            float m_new = m_s[tid];
#pragma unroll
            for (int t2 = 0; t2 < 16; t2++) m_new = fmaxf(m_new, red[tid * 16 + t2]);
            float a = __expf(m_s[tid] - m_new);
            al_s[tid] = a;
            m_s[tid]  = m_new;
            l_s[tid] *= a;
        }
        __syncthreads();   // (3)

        // p = exp(s - m), write Ps, partial row sums, rescale o
#pragma unroll
        for (int i = 0; i < 4; i++) {
            int q = ty + 16 * i;
            float mrow = m_s[q];
            float ps = 0.f;
#pragma unroll
            for (int j = 0; j < 4; j++) {
                float p = __expf(s[i][j] - mrow);
                Ps[q * 65 + tx + 16 * j] = p;
                ps += p;
            }
            red[q * 16 + tx] = ps;
            float a = al_s[q];
#pragma unroll
            for (int j = 0; j < 4; j++) o[i][j] *= a;
        }
        __syncthreads();   // (4)
        if (tid < 64) {
            float add = 0.f;
#pragma unroll
            for (int t2 = 0; t2 < 16; t2++) add += red[tid * 16 + t2];
            l_s[tid] += add;
        }

        // O += P @ V, thread tile [rows ty+16i][d cols tx+16j]
        for (int kv = 0; kv < 64; kv++) {
            float pv[4], vv[4];
#pragma unroll
            for (int i = 0; i < 4; i++) pv[i] = Ps[(ty + 16 * i) * 65 + kv];
#pragma unroll
            for (int j = 0; j < 4; j++) vv[j] = Vs[kv * 65 + tx + 16 * j];
#pragma unroll
            for (int i = 0; i < 4; i++)
#pragma unroll
                for (int j = 0; j < 4; j++) o[i][j] += pv[i] * vv[j];
        }
        __syncthreads();   // (5) tiles / Ps / red safe to overwrite
    }

#pragma unroll
    for (int i = 0; i < 4; i++) {
        int q = ty + 16 * i;
        float inv = 1.0f / l_s[q];
#pragma unroll
        for (int j = 0; j < 4; j++) {
            Op[(size_t)(b * SQ + q0 + q) * HID + h * DH + tx + 16 * j] = o[i][j] * inv;
        }
    }
}

// ----------------------------------------------------------------------
extern "C" void kernel_launch(void* const* d_in, const int* in_sizes, int n_in,
                              void* d_out, int out_size)
{
    (void)in_sizes; (void)n_in; (void)out_size;
    const float* inputs = (const float*)d_in[0];
    const float* latent = (const float*)d_in[1];
    const float* wq     = (const float*)d_in[2];
    const float* wk     = (const float*)d_in[3];
    const float* wv     = (const float*)d_in[4];
    const float* wo     = (const float*)d_in[5];
    const float* qnw    = (const float*)d_in[6];
    const float* knw    = (const float*)d_in[7];
    float* out = (float*)d_out;

    float *Qb, *Kb, *Vb, *AOb;
    cudaGetSymbolAddress((void**)&Qb,  g_Q);
    cudaGetSymbolAddress((void**)&Kb,  g_K);
    cudaGetSymbolAddress((void**)&Vb,  g_V);
    cudaGetSymbolAddress((void**)&AOb, g_AO);

    dim3 blk(256);

    // Q = rmsnorm(latent @ wq^T)   [1024, 1024]
    gemm_rt<true ><<<dim3(16, 16),  blk>>>(latent, wq, qnw, Qb, BATCH * SQ,  NH  * DH, HID);
    // K = rmsnorm(inputs @ wk^T)   [8192, 256]
    gemm_rt<true ><<<dim3(4, 128),  blk>>>(inputs, wk, knw, Kb, BATCH * SKV, NHK * DH, HID);
    // V = inputs @ wv^T            [8192, 256]
    gemm_rt<false><<<dim3(4, 128),  blk>>>(inputs, wv, nullptr, Vb, BATCH * SKV, NHK * DH, HID);

    // attention
    int smem_bytes = (4 * 64 * 65 + 3 * 64 + 64 * 16) * (int)sizeof(float);  // 71424
    cudaFuncSetAttribute(attn_kernel, cudaFuncAttributeMaxDynamicSharedMemorySize, smem_bytes);
    attn_kernel<<<dim3(SQ / 64, NH, BATCH), blk, smem_bytes>>>(Qb, Kb, Vb, AOb);

    // out = AO @ wo^T              [1024, 1024]
    gemm_rt<false><<<dim3(16, 16), blk>>>(AOb, wo, nullptr, out, BATCH * SQ, HID, HID);
}

// round 3
// speedup vs baseline: 2.2952x; 2.2952x over previous
#include <cuda_runtime.h>
#include <cstdint>

#define HID   1024
#define BATCH 2
#define SKV   4096
#define SQ    512
#define NH    16
#define NHK   4
#define DH    64

// ---------------- scratch ----------------
__device__ float g_Q [BATCH * SQ  * NH  * DH];
__device__ float g_K [BATCH * SKV * NHK * DH];
__device__ float g_V [BATCH * SKV * NHK * DH];
__device__ float g_AO[BATCH * SQ  * NH  * DH];

// ---------------- helpers ----------------
__device__ __forceinline__ uint32_t f2tf(float f) {
    uint32_t u;
    asm("cvt.rna.tf32.f32 %0, %1;" : "=r"(u) : "f"(f));
    return u;
}
// D += A * B  (m16n8k8 tf32, A row-major, B col-major)
__device__ __forceinline__ void mma8(float* d, const uint32_t* a, const uint32_t* b) {
    asm volatile(
        "mma.sync.aligned.m16n8k8.row.col.f32.tf32.tf32.f32 "
        "{%0,%1,%2,%3},{%4,%5,%6,%7},{%8,%9},{%0,%1,%2,%3};"
        : "+f"(d[0]), "+f"(d[1]), "+f"(d[2]), "+f"(d[3])
        : "r"(a[0]), "r"(a[1]), "r"(a[2]), "r"(a[3]), "r"(b[0]), "r"(b[1]));
}

// ======================================================================
// GEMM: C[M,N] = A[M,K] @ W[N,K]^T, tf32 mma.sync.
// PASSES=3: 3xTF32 (hi*hi + lo*hi + hi*lo) for near-fp32 accuracy.
// NORM: fused per-64-col-head RMSNorm epilogue.
// BM=128, BN=64, BK=32. 256 threads = 8 warps (4 M x 2 N), warp tile 32x32.
// ======================================================================
template <int PASSES, bool NORM>
__global__ void __launch_bounds__(256) gemm_tc(
    const float* __restrict__ A, const float* __restrict__ W,
    const float* __restrict__ nw, float* __restrict__ C,
    int M, int N, int Kdim)
{
    extern __shared__ float sm[];
    constexpr int AP = 36;  // pitch: (lane>>2)*36 + (lane&3) -> conflict-free
    float* Ahi = sm;
    float* Alo = Ahi + 128 * AP;
    float* Whi = Ahi + (PASSES == 3 ? 2 : 1) * 128 * AP;
    float* Wlo = Whi + 64 * AP;
    float* red = Whi + (PASSES == 3 ? 2 : 1) * 64 * AP;

    const int tid = threadIdx.x, lane = tid & 31, wid = tid >> 5;
    const int wm = wid >> 1, wn = wid & 1;
    const int g = lane >> 2, c = lane & 3;
    const int m0 = blockIdx.y * 128, n0 = blockIdx.x * 64;

    float acc[2][4][4];
#pragma unroll
    for (int mt = 0; mt < 2; mt++)
#pragma unroll
        for (int nt = 0; nt < 4; nt++)
#pragma unroll
            for (int i = 0; i < 4; i++) acc[mt][nt][i] = 0.f;

    const int arow = tid >> 1, acol = (tid & 1) * 16;
    const int wrow = tid >> 2, wcol = (tid & 3) * 8;
    const float* Ap = A + (size_t)(m0 + arow) * Kdim + acol;
    const float* Wp = W + (size_t)(n0 + wrow) * Kdim + wcol;

    for (int kt = 0; kt < Kdim; kt += 32) {
        // ---- stage A (128x32) and W (64x32), hi/lo tf32 split ----
#pragma unroll
        for (int i = 0; i < 4; i++) {
            float4 v = *(const float4*)(Ap + kt + i * 4);
            uint4 h;
            h.x = f2tf(v.x); h.y = f2tf(v.y); h.z = f2tf(v.z); h.w = f2tf(v.w);
            *(uint4*)(Ahi + arow * AP + acol + i * 4) = h;
            if constexpr (PASSES == 3) {
                uint4 l;
                l.x = f2tf(v.x - __uint_as_float(h.x));
                l.y = f2tf(v.y - __uint_as_float(h.y));
                l.z = f2tf(v.z - __uint_as_float(h.z));
                l.w = f2tf(v.w - __uint_as_float(h.w));
                *(uint4*)(Alo + arow * AP + acol + i * 4) = l;
            }
        }
#pragma unroll
        for (int i = 0; i < 2; i++) {
            float4 v = *(const float4*)(Wp + kt + i * 4);
            uint4 h;
            h.x = f2tf(v.x); h.y = f2tf(v.y); h.z = f2tf(v.z); h.w = f2tf(v.w);
            *(uint4*)(Whi + wrow * AP + wcol + i * 4) = h;
            if constexpr (PASSES == 3) {
                uint4 l;
                l.x = f2tf(v.x - __uint_as_float(h.x));
                l.y = f2tf(v.y - __uint_as_float(h.y));
                l.z = f2tf(v.z - __uint_as_float(h.z));
                l.w = f2tf(v.w - __uint_as_float(h.w));
                *(uint4*)(Wlo + wrow * AP + wcol + i * 4) = l;
            }
        }
        __syncthreads();

#pragma unroll
        for (int s = 0; s < 4; s++) {
            uint32_t ah[2][4], al[2][4], bh[4][2], bl[4][2];
#pragma unroll
            for (int mt = 0; mt < 2; mt++) {
                int r = wm * 32 + mt * 16;
                ah[mt][0] = __float_as_uint(Ahi[(r + g) * AP + s * 8 + c]);
                ah[mt][1] = __float_as_uint(Ahi[(r + g + 8) * AP + s * 8 + c]);
                ah[mt][2] = __float_as_uint(Ahi[(r + g) * AP + s * 8 + c + 4]);
                ah[mt][3] = __float_as_uint(Ahi[(r + g + 8) * AP + s * 8 + c + 4]);
                if constexpr (PASSES == 3) {
                    al[mt][0] = __float_as_uint(Alo[(r + g) * AP + s * 8 + c]);
                    al[mt][1] = __float_as_uint(Alo[(r + g + 8) * AP + s * 8 + c]);
                    al[mt][2] = __float_as_uint(Alo[(r + g) * AP + s * 8 + c + 4]);
                    al[mt][3] = __float_as_uint(Alo[(r + g + 8) * AP + s * 8 + c + 4]);
                }
            }
#pragma unroll
            for (int nt = 0; nt < 4; nt++) {
                int n = wn * 32 + nt * 8 + g;
                bh[nt][0] = __float_as_uint(Whi[n * AP + s * 8 + c]);
                bh[nt][1] = __float_as_uint(Whi[n * AP + s * 8 + c + 4]);
                if constexpr (PASSES == 3) {
                    bl[nt][0] = __float_as_uint(Wlo[n * AP + s * 8 + c]);
                    bl[nt][1] = __float_as_uint(Wlo[n * AP + s * 8 + c + 4]);
                }
            }
#pragma unroll
            for (int mt = 0; mt < 2; mt++)
#pragma unroll
                for (int nt = 0; nt < 4; nt++) {
                    mma8(acc[mt][nt], ah[mt], bh[nt]);
                    if constexpr (PASSES == 3) {
                        mma8(acc[mt][nt], al[mt], bh[nt]);
                        mma8(acc[mt][nt], ah[mt], bl[nt]);
                    }
                }
        }
        __syncthreads();
    }

    if (NORM) {
        float ss0[2] = {0.f, 0.f}, ss1[2] = {0.f, 0.f};
#pragma unroll
        for (int mt = 0; mt < 2; mt++)
#pragma unroll
            for (int nt = 0; nt < 4; nt++) {
                ss0[mt] += acc[mt][nt][0] * acc[mt][nt][0] + acc[mt][nt][1] * acc[mt][nt][1];
                ss1[mt] += acc[mt][nt][2] * acc[mt][nt][2] + acc[mt][nt][3] * acc[mt][nt][3];
            }
#pragma unroll
        for (int mt = 0; mt < 2; mt++) {
            ss0[mt] += __shfl_xor_sync(0xffffffffu, ss0[mt], 1);
            ss0[mt] += __shfl_xor_sync(0xffffffffu, ss0[mt], 2);
            ss1[mt] += __shfl_xor_sync(0xffffffffu, ss1[mt], 1);
            ss1[mt] += __shfl_xor_sync(0xffffffffu, ss1[mt], 2);
            if (c == 0) {
                red[(wm * 32 + mt * 16 + g) * 2 + wn]     = ss0[mt];
                red[(wm * 32 + mt * 16 + g + 8) * 2 + wn] = ss1[mt];
            }
        }
        __syncthreads();
        float sc0[2], sc1[2];
#pragma unroll
        for (int mt = 0; mt < 2; mt++) {
            int r = (wm * 32 + mt * 16 + g) * 2;
            sc0[mt] = rsqrtf((red[r] + red[r + 1]) * (1.f / 64.f) + 1e-6f);
            r = (wm * 32 + mt * 16 + g + 8) * 2;
            sc1[mt] = rsqrtf((red[r] + red[r + 1]) * (1.f / 64.f) + 1e-6f);
        }
        float w0[4], w1[4];
#pragma unroll
        for (int nt = 0; nt < 4; nt++) {
            w0[nt] = nw[wn * 32 + nt * 8 + 2 * c];
            w1[nt] = nw[wn * 32 + nt * 8 + 2 * c + 1];
        }
#pragma unroll
        for (int mt = 0; mt < 2; mt++)
#pragma unroll
            for (int nt = 0; nt < 4; nt++) {
                acc[mt][nt][0] *= sc0[mt] * w0[nt];
                acc[mt][nt][1] *= sc0[mt] * w1[nt];
                acc[mt][nt][2] *= sc1[mt] * w0[nt];
                acc[mt][nt][3] *= sc1[mt] * w1[nt];
            }
    }

#pragma unroll
    for (int mt = 0; mt < 2; mt++)
#pragma unroll
        for (int nt = 0; nt < 4; nt++) {
            int r = m0 + wm * 32 + mt * 16 + g;
            int col = n0 + wn * 32 + nt * 8 + 2 * c;
            *(float2*)(C + (size_t)r * N + col) =
                make_float2(acc[mt][nt][0], acc[mt][nt][1]);
            *(float2*)(C + (size_t)(r + 8) * N + col) =
                make_float2(acc[mt][nt][2], acc[mt][nt][3]);
        }
}

// ======================================================================
// Attention, mma.sync tf32. CTA = 128 rows (4 heads x 32 q) of one (b,hk).
// 8 warps x 16 rows. KV tile 64, double-buffered smem.
// QK^T in 3xTF32 (score abs-error amplifies through unscaled softmax);
// P@V in 1xTF32. No-max softmax: |s| <= 64 so exp stays finite in fp32.
// ======================================================================
__global__ void __launch_bounds__(256, 1) attn_mma(
    const float* __restrict__ Qg, const float* __restrict__ Kg,
    const float* __restrict__ Vg, float* __restrict__ Og)
{
    extern __shared__ float sm[];
    constexpr int KP = 68, VP = 72, PP = 76;
    constexpr int BUF = 64 * KP * 2 + 64 * VP;  // 13312 floats / buffer
    float* Ps = sm + 2 * BUF;

    const int tid = threadIdx.x;
    const int lane = tid & 31, w = tid >> 5;
    const int g = lane >> 2, c = lane & 3;
    const int b = blockIdx.z, hk = blockIdx.y, q0 = blockIdx.x * 32;
    const int head = hk * 4 + (w >> 1);
    const int qi = (w & 1) * 16;

    // ---- Q fragments (hi/lo tf32), persistent in registers ----
    uint32_t qh[8][4], ql[8][4];
    {
        const float* r0 = Qg + (size_t)(b * SQ + q0 + qi + g) * HID + head * DH;
        const float* r1 = r0 + 8 * (size_t)HID;
#pragma unroll
        for (int s = 0; s < 8; s++) {
            float f[4] = {r0[s * 8 + c], r1[s * 8 + c],
                          r0[s * 8 + c + 4], r1[s * 8 + c + 4]};
#pragma unroll
            for (int i = 0; i < 4; i++) {
                qh[s][i] = f2tf(f[i]);
                ql[s][i] = f2tf(f[i] - __uint_as_float(qh[s][i]));
            }
        }
    }

    const int krow = tid >> 2;
    const int kcol = (tid & 3) * 16;
    const float* kbase = Kg + (size_t)b * SKV * (NHK * DH) + hk * DH + kcol;
    const float* vbase = Vg + (size_t)b * SKV * (NHK * DH) + hk * DH + kcol;

    float4 kr[4], vr[4];
    auto LDG = [&](int t) {
        const float* kp = kbase + (size_t)(t * 64 + krow) * (NHK * DH);
        const float* vp = vbase + (size_t)(t * 64 + krow) * (NHK * DH);
#pragma unroll
        for (int i = 0; i < 4; i++) {
            kr[i] = *(const float4*)(kp + i * 4);
            vr[i] = *(const float4*)(vp + i * 4);
        }
    };
    auto STS = [&](int buf) {
        float* KH = sm + buf * BUF;
        float* KL = KH + 64 * KP;
        float* VV = KH + 64 * KP * 2;
#pragma unroll
        for (int i = 0; i < 4; i++) {
            uint4 h, l, v;
            h.x = f2tf(kr[i].x); l.x = f2tf(kr[i].x - __uint_as_float(h.x));
            h.y = f2tf(kr[i].y); l.y = f2tf(kr[i].y - __uint_as_float(h.y));
            h.z = f2tf(kr[i].z); l.z = f2tf(kr[i].z - __uint_as_float(h.z));
            h.w = f2tf(kr[i].w); l.w = f2tf(kr[i].w - __uint_as_float(h.w));
            *(uint4*)(KH + krow * KP + kcol + i * 4) = h;
            *(uint4*)(KL + krow * KP + kcol + i * 4) = l;
            v.x = f2tf(vr[i].x); v.y = f2tf(vr[i].y);
            v.z = f2tf(vr[i].z); v.w = f2tf(vr[i].w);
            *(uint4*)(VV + krow * VP + kcol + i * 4) = v;
        }
    };

    float oacc[8][4];
#pragma unroll
    for (int j = 0; j < 8; j++)
#pragma unroll
        for (int i = 0; i < 4; i++) oacc[j][i] = 0.f;
    float lsum0 = 0.f, lsum1 = 0.f;
    float* Pw = Ps + w * 16 * PP;

    LDG(0); STS(0);
    __syncthreads();

    for (int t = 0; t < SKV / 64; t++) {
        const int cur = t & 1;
        if (t < SKV / 64 - 1) LDG(t + 1);
        const float* KH = sm + cur * BUF;
        const float* KL = KH + 64 * KP;
        const float* VV = KH + 64 * KP * 2;

        // --- S = Q @ K^T (3xTF32) ---
        float sacc[8][4];
#pragma unroll
        for (int j = 0; j < 8; j++)
#pragma unroll
            for (int i = 0; i < 4; i++) sacc[j][i] = 0.f;
#pragma unroll
        for (int s = 0; s < 8; s++) {
#pragma unroll
            for (int j = 0; j < 8; j++) {
                const int ba = (j * 8 + g) * KP + s * 8 + c;
                uint32_t bh[2] = {__float_as_uint(KH[ba]), __float_as_uint(KH[ba + 4])};
                mma8(sacc[j], qh[s], bh);
                mma8(sacc[j], ql[s], bh);
                uint32_t bl[2] = {__float_as_uint(KL[ba]), __float_as_uint(KL[ba + 4])};
                mma8(sacc[j], qh[s], bl);
            }
        }

        // --- P = exp(S) (tf32-rounded), row sums ---
        float rs0 = 0.f, rs1 = 0.f;
#pragma unroll
        for (int j = 0; j < 8; j++) {
            uint32_t u0 = f2tf(__expf(sacc[j][0]));
            uint32_t u1 = f2tf(__expf(sacc[j][1]));
            uint32_t u2 = f2tf(__expf(sacc[j][2]));
            uint32_t u3 = f2tf(__expf(sacc[j][3]));
            rs0 += __uint_as_float(u0) + __uint_as_float(u1);
            rs1 += __uint_as_float(u2) + __uint_as_float(u3);
            *(uint2*)(Pw + g * PP + j * 8 + 2 * c)       = make_uint2(u0, u1);
            *(uint2*)(Pw + (g + 8) * PP + j * 8 + 2 * c) = make_uint2(u2, u3);
        }
        rs0 += __shfl_xor_sync(0xffffffffu, rs0, 1);
        rs0 += __shfl_xor_sync(0xffffffffu, rs0, 2);
        rs1 += __shfl_xor_sync(0xffffffffu, rs1, 1);
        rs1 += __shfl_xor_sync(0xffffffffu, rs1, 2);
        lsum0 += rs0;
        lsum1 += rs1;
        __syncwarp();

        // --- O += P @ V (1xTF32) ---
#pragma unroll
        for (int s = 0; s < 8; s++) {
            uint32_t a[4] = {
                __float_as_uint(Pw[g * PP + s * 8 + c]),
                __float_as_uint(Pw[(g + 8) * PP + s * 8 + c]),
                __float_as_uint(Pw[g * PP + s * 8 + c + 4]),
                __float_as_uint(Pw[(g + 8) * PP + s * 8 + c + 4])};
#pragma unroll
            for (int j = 0; j < 8; j++) {
                const int ba = (s * 8 + c) * VP + j * 8 + g;
                uint32_t bv[2] = {__float_as_uint(VV[ba]),
                                  __float_as_uint(VV[ba + 4 * VP])};
                mma8(oacc[j], a, bv);
            }
        }
        __syncwarp();

        if (t < SKV / 64 - 1) {
            __syncthreads();
            STS(1 - cur);
            __syncthreads();
        }
    }

    // --- epilogue: normalize, write ---
    const float i0 = 1.f / lsum0, i1 = 1.f / lsum1;
    float* o0 = Og + (size_t)(b * SQ + q0 + qi + g) * HID + head * DH;
    float* o1 = o0 + 8 * (size_t)HID;
#pragma unroll
    for (int j = 0; j < 8; j++) {
        *(float2*)(o0 + j * 8 + 2 * c) = make_float2(oacc[j][0] * i0, oacc[j][1] * i0);
        *(float2*)(o1 + j * 8 + 2 * c) = make_float2(oacc[j][2] * i1, oacc[j][3] * i1);
    }
}

// ======================================================================
extern "C" void kernel_launch(void* const* d_in, const int* in_sizes, int n_in,
                              void* d_out, int out_size)
{
    (void)in_sizes; (void)n_in; (void)out_size;
    const float* inputs = (const float*)d_in[0];
    const float* latent = (const float*)d_in[1];
    const float* wq     = (const float*)d_in[2];
    const float* wk     = (const float*)d_in[3];
    const float* wv     = (const float*)d_in[4];
    const float* wo     = (const float*)d_in[5];
    const float* qnw    = (const float*)d_in[6];
    const float* knw    = (const float*)d_in[7];
    float* out = (float*)d_out;

    float *Qb, *Kb, *Vb, *AOb;
    cudaGetSymbolAddress((void**)&Qb,  g_Q);
    cudaGetSymbolAddress((void**)&Kb,  g_K);
    cudaGetSymbolAddress((void**)&Vb,  g_V);
    cudaGetSymbolAddress((void**)&AOb, g_AO);

    const int SM3 = 56320;    // 3xTF32 GEMM smem
    const int SM1 = 28672;    // 1xTF32 GEMM smem
    const int SMA = 145408;   // attention smem
    cudaFuncSetAttribute(gemm_tc<3, true>,  cudaFuncAttributeMaxDynamicSharedMemorySize, SM3);
    cudaFuncSetAttribute(gemm_tc<1, false>, cudaFuncAttributeMaxDynamicSharedMemorySize, SM1);
    cudaFuncSetAttribute(attn_mma, cudaFuncAttributeMaxDynamicSharedMemorySize, SMA);

    dim3 blk(256);
    // Q = rmsnorm(latent @ wq^T), 3xTF32  [1024 x 1024]
    gemm_tc<3, true ><<<dim3(16, 8),  blk, SM3>>>(latent, wq, qnw, Qb, BATCH * SQ,  NH  * DH, HID);
    // K = rmsnorm(inputs @ wk^T), 3xTF32  [8192 x 256]
    gemm_tc<3, true ><<<dim3(4, 64),  blk, SM3>>>(inputs, wk, knw, Kb, BATCH * SKV, NHK * DH, HID);
    // V = inputs @ wv^T, 1xTF32           [8192 x 256]
    gemm_tc<1, false><<<dim3(4, 64),  blk, SM1>>>(inputs, wv, nullptr, Vb, BATCH * SKV, NHK * DH, HID);
    // attention
    attn_mma<<<dim3(SQ / 32, NHK, BATCH), blk, SMA>>>(Qb, Kb, Vb, AOb);
    // out = AO @ wo^T, 1xTF32             [1024 x 1024]
    gemm_tc<1, false><<<dim3(16, 8), blk, SM1>>>(AOb, wo, nullptr, out, BATCH * SQ, HID, HID);
}